// round 1
// baseline (speedup 1.0000x reference)
#include <cuda_runtime.h>
#include <cstdint>

// Problem constants (fixed shapes)
#define B_  4
#define T_  2048
#define D_  1024
#define H_  4
#define DK_ 256
#define DV_ 512
#define M_  (B_ * T_)        // 8192 rows
#define NKV (H_ * DK_)       // 1024
#define NV  (H_ * DV_)       // 2048

typedef unsigned long long ull;

// ---------------------------------------------------------------------------
// Scratch (device globals; no dynamic allocation allowed)
// ---------------------------------------------------------------------------
__device__ float g_normed[(size_t)M_ * D_];    // 32 MB
__device__ float g_q[(size_t)M_ * NKV];        // 32 MB
__device__ float g_k[(size_t)M_ * NKV];        // 32 MB
__device__ float g_v[(size_t)M_ * NV];         // 64 MB
__device__ float g_beta[(size_t)M_ * H_];      // 128 KB
__device__ float g_o[(size_t)M_ * NV];         // 64 MB (scan out, RMS-normed in place)

// ---------------------------------------------------------------------------
// f32x2 packed-FMA helpers (Blackwell FFMA2: 2 MACs / instruction)
// ---------------------------------------------------------------------------
__device__ __forceinline__ ull pack2(float x, float y) {
    ull r;
    asm("mov.b64 %0, {%1, %2};" : "=l"(r) : "f"(x), "f"(y));
    return r;
}
__device__ __forceinline__ void unpack2(ull v, float& x, float& y) {
    asm("mov.b64 {%0, %1}, %2;" : "=f"(x), "=f"(y) : "l"(v));
}
__device__ __forceinline__ void ffma2(ull& d, ull a, ull b) {
    asm("fma.rn.f32x2 %0, %1, %2, %0;" : "+l"(d) : "l"(a), "l"(b));
}

__device__ __forceinline__ float sigmoidf_(float x) {
    return 1.0f / (1.0f + __expf(-x));
}
__device__ __forceinline__ float siluf_(float x) {
    return x * sigmoidf_(x);
}

// ---------------------------------------------------------------------------
// 1) LayerNorm: x[8192,1024] -> g_normed
//    one block (256 thr) per row, float4 per thread
// ---------------------------------------------------------------------------
__global__ void __launch_bounds__(256) ln_kernel(const float* __restrict__ x,
                                                 const float* __restrict__ w,
                                                 const float* __restrict__ b) {
    const int row = blockIdx.x;
    const int tid = threadIdx.x;
    const float4 v = ((const float4*)(x + (size_t)row * D_))[tid];

    float s  = v.x + v.y + v.z + v.w;
    float s2 = v.x * v.x + v.y * v.y + v.z * v.z + v.w * v.w;

    #pragma unroll
    for (int off = 16; off > 0; off >>= 1) {
        s  += __shfl_xor_sync(0xffffffffu, s,  off);
        s2 += __shfl_xor_sync(0xffffffffu, s2, off);
    }
    __shared__ float sh[16];
    const int wid = tid >> 5, lane = tid & 31;
    if (lane == 0) { sh[wid] = s; sh[8 + wid] = s2; }
    __syncthreads();
    float ts = 0.f, ts2 = 0.f;
    #pragma unroll
    for (int i = 0; i < 8; ++i) { ts += sh[i]; ts2 += sh[8 + i]; }

    const float mean = ts * (1.0f / D_);
    const float var  = ts2 * (1.0f / D_) - mean * mean;
    const float rstd = rsqrtf(var + 1e-5f);

    const float4 wv = ((const float4*)w)[tid];
    const float4 bv = ((const float4*)b)[tid];
    float4 o;
    o.x = (v.x - mean) * rstd * wv.x + bv.x;
    o.y = (v.y - mean) * rstd * wv.y + bv.y;
    o.z = (v.z - mean) * rstd * wv.z + bv.z;
    o.w = (v.w - mean) * rstd * wv.w + bv.w;
    ((float4*)(g_normed + (size_t)row * D_))[tid] = o;
}

// ---------------------------------------------------------------------------
// 2) GEMM: C[M,N] = act(A[M,K] @ W[K,N]) (+ resid)
//    128x128x16 tile, 256 threads, 8x8 per thread, FFMA2 microkernel.
//    mode: 0 -> A=g_normed, C=g_q  (silu)
//          1 -> A=g_normed, C=g_k  (silu)
//          2 -> A=g_normed, C=g_v  (silu)
//          3 -> A=g_o,      C=Cext (none, + resid)
// ---------------------------------------------------------------------------
#define BM 128
#define BN 128
#define BK 16
#define BPAD 4

__global__ void __launch_bounds__(256, 1)
gemm_kernel(const float* __restrict__ W, float* __restrict__ Cext,
            const float* __restrict__ resid, int N, int K, int mode) {
    __shared__ float As[BK][BM + BPAD];
    __shared__ float Bs[BK][BN + BPAD];

    const float* A = (mode == 3) ? g_o : g_normed;
    float* C = (mode == 0) ? g_q : (mode == 1) ? g_k : (mode == 2) ? g_v : Cext;
    const bool do_silu = (mode < 3);

    const int tid = threadIdx.x;
    const int bm = blockIdx.y, bn = blockIdx.x;
    const int tm = tid >> 4, tn = tid & 15;   // 16x16 thread grid

    const float* Ab = A + (size_t)bm * BM * K;
    const float* Bb = W + (size_t)bn * BN;

    // A loads: idx = tid + 256*i -> row = idx/4, 4-col chunk = idx%4
    const int arow0 = tid >> 2;
    const int ac4   = tid & 3;
    // B loads: idx = tid + 256*i -> row = idx/32, col4 = (idx%32)*4
    const int brow0 = tid >> 5;
    const int bcol  = (tid & 31) * 4;

    ull acc[8][4];
    #pragma unroll
    for (int i = 0; i < 8; ++i)
        #pragma unroll
        for (int j = 0; j < 4; ++j) acc[i][j] = 0ull;

    const int KT = K / BK;
    float4 pa[2], pb[2];

    // prologue: load tile 0
    #pragma unroll
    for (int i = 0; i < 2; ++i) {
        pa[i] = *(const float4*)&Ab[(size_t)(arow0 + 64 * i) * K + ac4 * 4];
        pb[i] = *(const float4*)&Bb[(size_t)(brow0 + 8 * i) * N + bcol];
    }

    for (int kt = 0; kt < KT; ++kt) {
        __syncthreads();
        #pragma unroll
        for (int i = 0; i < 2; ++i) {
            const int r = arow0 + 64 * i;
            As[ac4 * 4 + 0][r] = pa[i].x;
            As[ac4 * 4 + 1][r] = pa[i].y;
            As[ac4 * 4 + 2][r] = pa[i].z;
            As[ac4 * 4 + 3][r] = pa[i].w;
            *(float4*)&Bs[brow0 + 8 * i][bcol] = pb[i];
        }
        __syncthreads();

        if (kt + 1 < KT) {
            const int k0 = (kt + 1) * BK;
            #pragma unroll
            for (int i = 0; i < 2; ++i) {
                pa[i] = *(const float4*)&Ab[(size_t)(arow0 + 64 * i) * K + k0 + ac4 * 4];
                pb[i] = *(const float4*)&Bb[(size_t)(k0 + brow0 + 8 * i) * N + bcol];
            }
        }

        #pragma unroll
        for (int kk = 0; kk < BK; ++kk) {
            const float4 a0 = *(const float4*)&As[kk][tm * 8];
            const float4 a1 = *(const float4*)&As[kk][tm * 8 + 4];
            ull a2[8];
            a2[0] = pack2(a0.x, a0.x); a2[1] = pack2(a0.y, a0.y);
            a2[2] = pack2(a0.z, a0.z); a2[3] = pack2(a0.w, a0.w);
            a2[4] = pack2(a1.x, a1.x); a2[5] = pack2(a1.y, a1.y);
            a2[6] = pack2(a1.z, a1.z); a2[7] = pack2(a1.w, a1.w);
            const ulonglong2 b01 = *(const ulonglong2*)&Bs[kk][tn * 8];
            const ulonglong2 b23 = *(const ulonglong2*)&Bs[kk][tn * 8 + 4];
            const ull bb0 = b01.x, bb1 = b01.y, bb2 = b23.x, bb3 = b23.y;
            #pragma unroll
            for (int i = 0; i < 8; ++i) {
                ffma2(acc[i][0], a2[i], bb0);
                ffma2(acc[i][1], a2[i], bb1);
                ffma2(acc[i][2], a2[i], bb2);
                ffma2(acc[i][3], a2[i], bb3);
            }
        }
    }

    // epilogue
    #pragma unroll
    for (int i = 0; i < 8; ++i) {
        float r[8];
        #pragma unroll
        for (int j = 0; j < 4; ++j) unpack2(acc[i][j], r[2 * j], r[2 * j + 1]);
        if (do_silu) {
            #pragma unroll
            for (int j = 0; j < 8; ++j) r[j] = siluf_(r[j]);
        }
        const size_t row = (size_t)bm * BM + tm * 8 + i;
        const size_t cb  = (size_t)bn * BN + tn * 8;
        if (resid != nullptr) {
            #pragma unroll
            for (int j = 0; j < 8; ++j) r[j] += resid[row * N + cb + j];
        }
        float4 w0 = make_float4(r[0], r[1], r[2], r[3]);
        float4 w1 = make_float4(r[4], r[5], r[6], r[7]);
        *(float4*)&C[row * N + cb]     = w0;
        *(float4*)&C[row * N + cb + 4] = w1;
    }
}

// ---------------------------------------------------------------------------
// 3) beta = sigmoid(normed @ Wb), Wb[1024,4]; one warp per row m
// ---------------------------------------------------------------------------
__global__ void __launch_bounds__(256) beta_kernel(const float* __restrict__ Wb) {
    const int warp = (blockIdx.x * blockDim.x + threadIdx.x) >> 5;
    const int lane = threadIdx.x & 31;
    if (warp >= M_) return;
    const float* nr = g_normed + (size_t)warp * D_;
    float a0 = 0, a1 = 0, a2 = 0, a3 = 0;
    for (int d = lane; d < D_; d += 32) {
        const float xn = nr[d];
        const float4 wv = *(const float4*)&Wb[d * 4];
        a0 += xn * wv.x; a1 += xn * wv.y; a2 += xn * wv.z; a3 += xn * wv.w;
    }
    #pragma unroll
    for (int off = 16; off > 0; off >>= 1) {
        a0 += __shfl_xor_sync(0xffffffffu, a0, off);
        a1 += __shfl_xor_sync(0xffffffffu, a1, off);
        a2 += __shfl_xor_sync(0xffffffffu, a2, off);
        a3 += __shfl_xor_sync(0xffffffffu, a3, off);
    }
    if (lane == 0) {
        float4 o = make_float4(sigmoidf_(a0), sigmoidf_(a1), sigmoidf_(a2), sigmoidf_(a3));
        *(float4*)&g_beta[(size_t)warp * 4] = o;
    }
}

// ---------------------------------------------------------------------------
// 4) l2norm over 256-element head groups of g_q (with *DK^-0.5) and g_k.
//    one warp per group (8 floats / lane); grid.y: 0 -> q, 1 -> k
// ---------------------------------------------------------------------------
__global__ void __launch_bounds__(256) l2norm_kernel() {
    const int grp  = blockIdx.x * 8 + (threadIdx.x >> 5);  // m*H + h
    const int lane = threadIdx.x & 31;
    float* base = ((blockIdx.y == 0) ? g_q : g_k) + (size_t)grp * DK_;
    float4 v0 = ((const float4*)base)[lane];
    float4 v1 = ((const float4*)base)[lane + 32];
    float ss = v0.x * v0.x + v0.y * v0.y + v0.z * v0.z + v0.w * v0.w
             + v1.x * v1.x + v1.y * v1.y + v1.z * v1.z + v1.w * v1.w;
    #pragma unroll
    for (int off = 16; off > 0; off >>= 1) ss += __shfl_xor_sync(0xffffffffu, ss, off);
    float sc = rsqrtf(ss + 1e-6f);
    if (blockIdx.y == 0) sc *= 0.0625f;  // DK^-0.5
    v0.x *= sc; v0.y *= sc; v0.z *= sc; v0.w *= sc;
    v1.x *= sc; v1.y *= sc; v1.z *= sc; v1.w *= sc;
    ((float4*)base)[lane]      = v0;
    ((float4*)base)[lane + 32] = v1;
}

// ---------------------------------------------------------------------------
// 5) Delta-rule scan. grid = B*H*8 = 128 CTAs, 256 threads.
//    CTA (b,h,c): dv chunk [c*64, c*64+64). Thread (g = tid&7, cp = tid>>3)
//    owns dk in [g*32, g*32+32), dv = {dv0+2cp, dv0+2cp+1} -> 64 state regs.
//    Reductions over dk across the 8-lane group via shfl_xor.
// ---------------------------------------------------------------------------
__global__ void __launch_bounds__(256, 1) scan_kernel() {
    const int blk = blockIdx.x;
    const int c = blk & 7;
    const int h = (blk >> 3) & 3;
    const int b = blk >> 5;
    const int dv0 = c * 64;
    const int tid = threadIdx.x;
    const int g  = tid & 7;
    const int cp = tid >> 3;

    __shared__ float ks[2][256], qs[2][256], vs[2][64], bs[2];

    float S0[32], S1[32];
    #pragma unroll
    for (int i = 0; i < 32; ++i) { S0[i] = 0.f; S1[i] = 0.f; }

    const size_t mbase = (size_t)b * T_;

    // preload t = 0
    {
        const size_t m = mbase;
        ks[0][tid] = g_k[m * NKV + h * DK_ + tid];
        qs[0][tid] = g_q[m * NKV + h * DK_ + tid];
        if (tid < 64) vs[0][tid] = g_v[m * NV + h * DV_ + dv0 + tid];
        if (tid == 0) bs[0] = g_beta[m * H_ + h];
    }
    __syncthreads();

    for (int t = 0; t < T_; ++t) {
        const int cur = t & 1, nxt = cur ^ 1;

        // prefetch step t+1 into registers (latency hidden under compute)
        float pk = 0.f, pq = 0.f, pv = 0.f, pb = 0.f;
        if (t + 1 < T_) {
            const size_t m = mbase + t + 1;
            pk = g_k[m * NKV + h * DK_ + tid];
            pq = g_q[m * NKV + h * DK_ + tid];
            if (tid < 64) pv = g_v[m * NV + h * DV_ + dv0 + tid];
            if (tid == 0) pb = g_beta[m * H_ + h];
        }

        float kr[32], qr[32];
        #pragma unroll
        for (int i = 0; i < 8; ++i) {
            const float4 t4 = *(const float4*)&ks[cur][g * 32 + i * 4];
            kr[4 * i] = t4.x; kr[4 * i + 1] = t4.y; kr[4 * i + 2] = t4.z; kr[4 * i + 3] = t4.w;
            const float4 u4 = *(const float4*)&qs[cur][g * 32 + i * 4];
            qr[4 * i] = u4.x; qr[4 * i + 1] = u4.y; qr[4 * i + 2] = u4.z; qr[4 * i + 3] = u4.w;
        }
        const float v0 = vs[cur][cp * 2], v1 = vs[cur][cp * 2 + 1];
        const float bt = bs[cur];

        // pred = k^T S_old (partial over this thread's dk, reduce over 8 lanes)
        float p0 = 0.f, p1 = 0.f;
        #pragma unroll
        for (int i = 0; i < 32; ++i) { p0 += kr[i] * S0[i]; p1 += kr[i] * S1[i]; }
        #pragma unroll
        for (int off = 1; off < 8; off <<= 1) {
            p0 += __shfl_xor_sync(0xffffffffu, p0, off);
            p1 += __shfl_xor_sync(0xffffffffu, p1, off);
        }
        const float vd0 = bt * (v0 - p0);
        const float vd1 = bt * (v1 - p1);

        // S_new = S_old + k vd^T ;  o = q^T S_new
        float o0 = 0.f, o1 = 0.f;
        #pragma unroll
        for (int i = 0; i < 32; ++i) {
            S0[i] += kr[i] * vd0;  o0 += qr[i] * S0[i];
            S1[i] += kr[i] * vd1;  o1 += qr[i] * S1[i];
        }
        #pragma unroll
        for (int off = 1; off < 8; off <<= 1) {
            o0 += __shfl_xor_sync(0xffffffffu, o0, off);
            o1 += __shfl_xor_sync(0xffffffffu, o1, off);
        }
        if (g == 0) {
            float2 st; st.x = o0; st.y = o1;
            *(float2*)&g_o[(mbase + t) * NV + h * DV_ + dv0 + cp * 2] = st;
        }

        // stage t+1
        ks[nxt][tid] = pk;
        qs[nxt][tid] = pq;
        if (tid < 64) vs[nxt][tid] = pv;
        if (tid == 0) bs[nxt] = pb;
        __syncthreads();
    }
}

// ---------------------------------------------------------------------------
// 6) per-head RMSNorm on g_o (in place): groups of 512, one warp per group
// ---------------------------------------------------------------------------
__global__ void __launch_bounds__(256) rmsnorm_kernel(const float* __restrict__ w) {
    const int grp  = blockIdx.x * 8 + (threadIdx.x >> 5);  // m*H + h
    const int lane = threadIdx.x & 31;
    float* base = g_o + (size_t)grp * DV_;
    float4 v[4];
    float ss = 0.f;
    #pragma unroll
    for (int i = 0; i < 4; ++i) {
        v[i] = ((const float4*)base)[lane + 32 * i];
        ss += v[i].x * v[i].x + v[i].y * v[i].y + v[i].z * v[i].z + v[i].w * v[i].w;
    }
    #pragma unroll
    for (int off = 16; off > 0; off >>= 1) ss += __shfl_xor_sync(0xffffffffu, ss, off);
    const float rs = rsqrtf(ss * (1.0f / DV_) + 1e-5f);
    #pragma unroll
    for (int i = 0; i < 4; ++i) {
        const int idx = lane + 32 * i;
        const float4 wv = ((const float4*)w)[idx];
        float4 o;
        o.x = v[i].x * rs * wv.x; o.y = v[i].y * rs * wv.y;
        o.z = v[i].z * rs * wv.z; o.w = v[i].w * rs * wv.w;
        ((float4*)base)[idx] = o;
    }
}

// ---------------------------------------------------------------------------
// Launch
// ---------------------------------------------------------------------------
extern "C" void kernel_launch(void* const* d_in, const int* in_sizes, int n_in,
                              void* d_out, int out_size) {
    const float* x        = (const float*)d_in[0];
    const float* ln_w     = (const float*)d_in[1];
    const float* ln_b     = (const float*)d_in[2];
    const float* Wq       = (const float*)d_in[3];
    const float* Wk       = (const float*)d_in[4];
    const float* Wv       = (const float*)d_in[5];
    const float* Wb       = (const float*)d_in[6];
    const float* o_norm_w = (const float*)d_in[7];
    const float* Wo       = (const float*)d_in[8];
    float* out = (float*)d_out;

    // 1) LayerNorm
    ln_kernel<<<M_, 256>>>(x, ln_w, ln_b);

    // 2) projections (silu fused into GEMM epilogue)
    gemm_kernel<<<dim3(NKV / BN, M_ / BM), 256>>>(Wq, nullptr, nullptr, NKV, D_, 0);
    gemm_kernel<<<dim3(NKV / BN, M_ / BM), 256>>>(Wk, nullptr, nullptr, NKV, D_, 1);
    gemm_kernel<<<dim3(NV  / BN, M_ / BM), 256>>>(Wv, nullptr, nullptr, NV,  D_, 2);

    // 3) beta
    beta_kernel<<<M_ / 8, 256>>>(Wb);

    // 4) l2norm on q (with DK^-0.5) and k
    l2norm_kernel<<<dim3((M_ * H_) / 8, 2), 256>>>();

    // 5) delta-rule scan
    scan_kernel<<<B_ * H_ * 8, 256>>>();

    // 6) per-head RMSNorm (in place on g_o)
    rmsnorm_kernel<<<(M_ * H_) / 8, 256>>>(o_norm_w);

    // 7) output projection + residual
    gemm_kernel<<<dim3(D_ / BN, M_ / BM), 256>>>(Wo, out, x, D_, NV, 3);
}